// round 4
// baseline (speedup 1.0000x reference)
#include <cuda_runtime.h>

#define FH 128
#define FO 64
#define NMAX 50048

// ---------------- scratch (device globals: no allocation allowed) ------------
__device__ float g_H1[(size_t)NMAX * FH];   // x @ W1
__device__ float g_A1[(size_t)NMAX * FH];   // layer-1 edge aggregation
__device__ float g_HG2[(size_t)NMAX * FO];  // bnrelu(h) @ W2
__device__ float g_A2[(size_t)NMAX * FO];   // layer-2 edge aggregation
__device__ float g_dinv1[NMAX];
__device__ float g_dinv2[NMAX];
__device__ float g_sum[FH];
__device__ float g_sumsq[FH];
__device__ float g_scale[FH];
__device__ float g_shift[FH];

// ---------------- zero accumulators ------------------------------------------
__global__ void zero_kernel(int N) {
    int i = blockIdx.x * blockDim.x + threadIdx.x;
    if (i < N * FH)  g_A1[i] = 0.f;
    if (i < N * FO)  g_A2[i] = 0.f;
    if (i < N)       { g_dinv1[i] = 0.f; g_dinv2[i] = 0.f; }
    if (i < FH)      { g_sum[i] = 0.f; g_sumsq[i] = 0.f; }
}

// ---------------- degree count (dst side, both graphs) -----------------------
__global__ void deg_kernel(const int* __restrict__ e1,
                           const int* __restrict__ e2, int E) {
    int i = blockIdx.x * blockDim.x + threadIdx.x;
    if (i < E) {
        atomicAdd(&g_dinv1[e1[E + i]], 1.0f);
        atomicAdd(&g_dinv2[e2[E + i]], 1.0f);
    }
}

__global__ void dinv_kernel(int N) {
    int i = blockIdx.x * blockDim.x + threadIdx.x;
    if (i < N) {
        g_dinv1[i] = rsqrtf(g_dinv1[i] + 1.0f);  // +1 = self loop; always > 0
        g_dinv2[i] = rsqrtf(g_dinv2[i] + 1.0f);
    }
}

// ---------------- GEMM: out[:, col0:col0+64] = X[N x 128] @ W[128 x LD] ------
// BM=128, BN=64, BK=32, 256 threads, 8x4 register tile. Static smem only.
// DO_BN: y = max(0, x*scale[k]+shift[k]) applied to X while loading (layer 2).
template <bool DO_BN>
__global__ void __launch_bounds__(256)
gemm_kernel(const float* __restrict__ X, const float* __restrict__ W, int N) {
    constexpr int LD = DO_BN ? FO : FH;  // width of W and of out
    __shared__ float XsT[32][132];       // k-major transposed X tile
    __shared__ float Ws[32][68];
    float* out = DO_BN ? g_HG2 : g_H1;

    const int row0 = blockIdx.x * 128;
    const int col0 = blockIdx.y * 64;
    const int tid  = threadIdx.x;
    const int tx   = tid & 15;   // 16 col groups * 4 cols
    const int ty   = tid >> 4;   // 16 row groups * 8 rows

    float acc[8][4];
#pragma unroll
    for (int i = 0; i < 8; i++)
#pragma unroll
        for (int j = 0; j < 4; j++) acc[i][j] = 0.f;

    for (int kc = 0; kc < FH; kc += 32) {
        __syncthreads();  // protect smem from previous iteration's readers
        // load X tile: 128 rows x 32 k (8 float4 per row), transposed store
        for (int i = tid; i < 1024; i += 256) {
            int r = i >> 3, c4 = i & 7;
            int row = row0 + r;
            float4 v = make_float4(0.f, 0.f, 0.f, 0.f);
            if (row < N)
                v = reinterpret_cast<const float4*>(X + (size_t)row * FH + kc)[c4];
            int k0 = c4 * 4;
            if (DO_BN) {
                int g = kc + k0;
                v.x = fmaxf(fmaf(v.x, g_scale[g + 0], g_shift[g + 0]), 0.f);
                v.y = fmaxf(fmaf(v.y, g_scale[g + 1], g_shift[g + 1]), 0.f);
                v.z = fmaxf(fmaf(v.z, g_scale[g + 2], g_shift[g + 2]), 0.f);
                v.w = fmaxf(fmaf(v.w, g_scale[g + 3], g_shift[g + 3]), 0.f);
            }
            XsT[k0 + 0][r] = v.x;
            XsT[k0 + 1][r] = v.y;
            XsT[k0 + 2][r] = v.z;
            XsT[k0 + 3][r] = v.w;
        }
        // load W tile: 32 k x 64 cols (16 float4 per k-row)
        for (int i = tid; i < 512; i += 256) {
            int k = i >> 4, c4 = i & 15;
            reinterpret_cast<float4*>(&Ws[k][0])[c4] =
                reinterpret_cast<const float4*>(W + (size_t)(kc + k) * LD + col0)[c4];
        }
        __syncthreads();

#pragma unroll
        for (int k = 0; k < 32; ++k) {
            float4 a0 = *reinterpret_cast<const float4*>(&XsT[k][ty * 8]);
            float4 a1 = *reinterpret_cast<const float4*>(&XsT[k][ty * 8 + 4]);
            float4 b  = *reinterpret_cast<const float4*>(&Ws[k][tx * 4]);
            float av[8] = {a0.x, a0.y, a0.z, a0.w, a1.x, a1.y, a1.z, a1.w};
            float bv[4] = {b.x, b.y, b.z, b.w};
#pragma unroll
            for (int i = 0; i < 8; i++)
#pragma unroll
                for (int j = 0; j < 4; j++)
                    acc[i][j] = fmaf(av[i], bv[j], acc[i][j]);
        }
    }

#pragma unroll
    for (int i = 0; i < 8; i++) {
        int row = row0 + ty * 8 + i;
        if (row < N) {
            *reinterpret_cast<float4*>(&out[(size_t)row * LD + col0 + tx * 4]) =
                make_float4(acc[i][0], acc[i][1], acc[i][2], acc[i][3]);
        }
    }
}

// ---------------- edge scatter: A[dst] += dinv[s]*dinv[d] * H[src] -----------
template <int LAYER>
__global__ void scatter_kernel(const int* __restrict__ ei, int E) {
    constexpr int F = (LAYER == 1) ? FH : FO;
    constexpr int C = F / 4;  // float4 chunks per edge
    const float* dinv = (LAYER == 1) ? g_dinv1 : g_dinv2;
    const float* H    = (LAYER == 1) ? g_H1    : g_HG2;
    float*       A    = (LAYER == 1) ? g_A1    : g_A2;

    long long t = (long long)blockIdx.x * blockDim.x + threadIdx.x;
    long long edge = t / C;
    int comp = (int)(t % C);
    if (edge >= E) return;
    int s = ei[edge];
    int d = ei[E + edge];
    float w = dinv[s] * dinv[d];
    float4 v = reinterpret_cast<const float4*>(H)[(size_t)s * C + comp];
    float* a = A + (size_t)d * F + comp * 4;
    atomicAdd(a + 0, w * v.x);
    atomicAdd(a + 1, w * v.y);
    atomicAdd(a + 2, w * v.z);
    atomicAdd(a + 3, w * v.w);
}

// ---------------- finalize layer 1: hidden = A1 + dinv^2*H1 + b1; BN stats ---
__global__ void finalize1_kernel(const float* __restrict__ b1,
                                 float* __restrict__ hidden, int N) {
    int f = threadIdx.x;  // 128 threads = features
    int r0 = blockIdx.x * 64;
    int r1 = min(r0 + 64, N);
    float bias = b1[f];
    float s = 0.f, sq = 0.f;
    for (int r = r0; r < r1; ++r) {
        float di = g_dinv1[r];
        float v = g_A1[(size_t)r * FH + f] + di * di * g_H1[(size_t)r * FH + f] + bias;
        hidden[(size_t)r * FH + f] = v;
        s += v;
        sq += v * v;
    }
    atomicAdd(&g_sum[f], s);
    atomicAdd(&g_sumsq[f], sq);
}

// ---------------- BN scale/shift from batch stats ----------------------------
__global__ void bnprep_kernel(const float* __restrict__ gamma,
                              const float* __restrict__ beta, float invN) {
    int f = threadIdx.x;
    float mean = g_sum[f] * invN;
    float var  = g_sumsq[f] * invN - mean * mean;  // biased, like torch BN
    float sc = gamma[f] * rsqrtf(var + 1e-5f);
    g_scale[f] = sc;
    g_shift[f] = beta[f] - mean * sc;
}

// ---------------- finalize layer 2: out = A2 + dinv2^2*HG2 + b2 --------------
__global__ void finalize2_kernel(const float* __restrict__ b2,
                                 float* __restrict__ out, int N) {
    int i = blockIdx.x * blockDim.x + threadIdx.x;
    if (i < N * FO) {
        int r = i >> 6, f = i & 63;
        float di = g_dinv2[r];
        out[i] = g_A2[i] + di * di * g_HG2[i] + b2[f];
    }
}

// ---------------- launch -----------------------------------------------------
extern "C" void kernel_launch(void* const* d_in, const int* in_sizes, int n_in,
                              void* d_out, int out_size) {
    const float* x     = (const float*)d_in[0];
    const int*   e1    = (const int*)d_in[1];
    const int*   e2    = (const int*)d_in[2];
    const float* W1    = (const float*)d_in[3];
    const float* b1    = (const float*)d_in[4];
    const float* gamma = (const float*)d_in[5];
    const float* beta  = (const float*)d_in[6];
    const float* W2    = (const float*)d_in[7];
    const float* b2    = (const float*)d_in[8];

    int N = in_sizes[0] / FH;
    int E = in_sizes[1] / 2;

    float* out    = (float*)d_out;            // [N, 64]
    float* hidden = out + (size_t)N * FO;     // [N, 128]

    zero_kernel<<<(N * FH + 255) / 256, 256>>>(N);
    deg_kernel<<<(E + 255) / 256, 256>>>(e1, e2, E);
    dinv_kernel<<<(N + 255) / 256, 256>>>(N);

    int gm = (N + 127) / 128;

    // layer 1
    gemm_kernel<false><<<dim3(gm, 2), 256>>>(x, W1, N);
    {
        long long threads = (long long)E * (FH / 4);
        scatter_kernel<1><<<(unsigned)((threads + 255) / 256), 256>>>(e1, E);
    }
    finalize1_kernel<<<(N + 63) / 64, FH>>>(b1, hidden, N);
    bnprep_kernel<<<1, FH>>>(gamma, beta, 1.0f / (float)N);

    // layer 2 (BN + ReLU fused into GEMM2 operand load)
    gemm_kernel<true><<<dim3(gm, 1), 256>>>(hidden, W2, N);
    {
        long long threads = (long long)E * (FO / 4);
        scatter_kernel<2><<<(unsigned)((threads + 255) / 256), 256>>>(e2, E);
    }
    finalize2_kernel<<<(N * FO + 255) / 256, 256>>>(b2, out, N);
}

// round 7
// speedup vs baseline: 1.6307x; 1.6307x over previous
#include <cuda_runtime.h>

#define FH 128
#define FO 64
#define NMAX 50048

// ---------------- scratch (device globals: no allocation allowed) ------------
__device__ float g_H1[(size_t)NMAX * FH];   // x @ W1
__device__ float g_A1[(size_t)NMAX * FH];   // layer-1 edge aggregation
__device__ float g_HG2[(size_t)NMAX * FO];  // bnrelu(h) @ W2
__device__ float g_A2[(size_t)NMAX * FO];   // layer-2 edge aggregation
__device__ float g_dinv1[NMAX];
__device__ float g_dinv2[NMAX];
__device__ float g_sum[FH];
__device__ float g_sumsq[FH];
__device__ float g_scale[FH];
__device__ float g_shift[FH];

// one-instruction 4-float global reduction (sm_90+)
__device__ __forceinline__ void red_add_v4(float* addr, float a, float b,
                                           float c, float d) {
    asm volatile("red.global.add.v4.f32 [%0], {%1, %2, %3, %4};"
                 :: "l"(addr), "f"(a), "f"(b), "f"(c), "f"(d)
                 : "memory");
}

// ---------------- zero accumulators ------------------------------------------
__global__ void zero_kernel(int N) {
    int i = blockIdx.x * blockDim.x + threadIdx.x;
    if (i < N * FH)  g_A1[i] = 0.f;
    if (i < N * FO)  g_A2[i] = 0.f;
    if (i < N)       { g_dinv1[i] = 0.f; g_dinv2[i] = 0.f; }
    if (i < FH)      { g_sum[i] = 0.f; g_sumsq[i] = 0.f; }
}

// ---------------- degree count (dst side, both graphs) -----------------------
__global__ void deg_kernel(const int* __restrict__ e1,
                           const int* __restrict__ e2, int E) {
    int i = blockIdx.x * blockDim.x + threadIdx.x;
    if (i < E) {
        atomicAdd(&g_dinv1[e1[E + i]], 1.0f);
        atomicAdd(&g_dinv2[e2[E + i]], 1.0f);
    }
}

__global__ void dinv_kernel(int N) {
    int i = blockIdx.x * blockDim.x + threadIdx.x;
    if (i < N) {
        g_dinv1[i] = rsqrtf(g_dinv1[i] + 1.0f);  // +1 = self loop; always > 0
        g_dinv2[i] = rsqrtf(g_dinv2[i] + 1.0f);
    }
}

// ---------------- GEMM: out[:, col0:col0+64] = X[N x 128] @ W[128 x LD] ------
// BM=128, BN=64, BK=32, 256 threads, 8x4 register tile. Static smem only.
// DO_BN: y = max(0, x*scale[k]+shift[k]) applied to X while loading (layer 2).
template <bool DO_BN>
__global__ void __launch_bounds__(256)
gemm_kernel(const float* __restrict__ X, const float* __restrict__ W, int N) {
    constexpr int LD = DO_BN ? FO : FH;  // width of W and of out
    __shared__ float XsT[32][132];       // k-major transposed X tile
    __shared__ float Ws[32][68];
    float* out = DO_BN ? g_HG2 : g_H1;

    const int row0 = blockIdx.x * 128;
    const int col0 = blockIdx.y * 64;
    const int tid  = threadIdx.x;
    const int tx   = tid & 15;   // 16 col groups * 4 cols
    const int ty   = tid >> 4;   // 16 row groups * 8 rows

    float acc[8][4];
#pragma unroll
    for (int i = 0; i < 8; i++)
#pragma unroll
        for (int j = 0; j < 4; j++) acc[i][j] = 0.f;

    for (int kc = 0; kc < FH; kc += 32) {
        __syncthreads();  // protect smem from previous iteration's readers
        // load X tile: 128 rows x 32 k (8 float4 per row), transposed store
        for (int i = tid; i < 1024; i += 256) {
            int r = i >> 3, c4 = i & 7;
            int row = row0 + r;
            float4 v = make_float4(0.f, 0.f, 0.f, 0.f);
            if (row < N)
                v = reinterpret_cast<const float4*>(X + (size_t)row * FH + kc)[c4];
            int k0 = c4 * 4;
            if (DO_BN) {
                int g = kc + k0;
                v.x = fmaxf(fmaf(v.x, g_scale[g + 0], g_shift[g + 0]), 0.f);
                v.y = fmaxf(fmaf(v.y, g_scale[g + 1], g_shift[g + 1]), 0.f);
                v.z = fmaxf(fmaf(v.z, g_scale[g + 2], g_shift[g + 2]), 0.f);
                v.w = fmaxf(fmaf(v.w, g_scale[g + 3], g_shift[g + 3]), 0.f);
            }
            XsT[k0 + 0][r] = v.x;
            XsT[k0 + 1][r] = v.y;
            XsT[k0 + 2][r] = v.z;
            XsT[k0 + 3][r] = v.w;
        }
        // load W tile: 32 k x 64 cols (16 float4 per k-row)
        for (int i = tid; i < 512; i += 256) {
            int k = i >> 4, c4 = i & 15;
            reinterpret_cast<float4*>(&Ws[k][0])[c4] =
                reinterpret_cast<const float4*>(W + (size_t)(kc + k) * LD + col0)[c4];
        }
        __syncthreads();

#pragma unroll
        for (int k = 0; k < 32; ++k) {
            float4 a0 = *reinterpret_cast<const float4*>(&XsT[k][ty * 8]);
            float4 a1 = *reinterpret_cast<const float4*>(&XsT[k][ty * 8 + 4]);
            float4 b  = *reinterpret_cast<const float4*>(&Ws[k][tx * 4]);
            float av[8] = {a0.x, a0.y, a0.z, a0.w, a1.x, a1.y, a1.z, a1.w};
            float bv[4] = {b.x, b.y, b.z, b.w};
#pragma unroll
            for (int i = 0; i < 8; i++)
#pragma unroll
                for (int j = 0; j < 4; j++)
                    acc[i][j] = fmaf(av[i], bv[j], acc[i][j]);
        }
    }

#pragma unroll
    for (int i = 0; i < 8; i++) {
        int row = row0 + ty * 8 + i;
        if (row < N) {
            *reinterpret_cast<float4*>(&out[(size_t)row * LD + col0 + tx * 4]) =
                make_float4(acc[i][0], acc[i][1], acc[i][2], acc[i][3]);
        }
    }
}

// ---------------- layer-1 scatter: warp per edge (32 lanes x float4 = 128) ---
__global__ void __launch_bounds__(256)
scatter1_kernel(const int* __restrict__ ei, int E) {
    int warp = (blockIdx.x * blockDim.x + threadIdx.x) >> 5;
    int lane = threadIdx.x & 31;
    if (warp >= E) return;
    int s = 0, d = 0;
    if (lane == 0) { s = ei[warp]; d = ei[E + warp]; }
    s = __shfl_sync(0xffffffffu, s, 0);
    d = __shfl_sync(0xffffffffu, d, 0);
    float w = g_dinv1[s] * g_dinv1[d];
    float4 v = reinterpret_cast<const float4*>(g_H1)[(size_t)s * 32 + lane];
    red_add_v4(&g_A1[(size_t)d * FH + lane * 4], w * v.x, w * v.y, w * v.z,
               w * v.w);
}

// ---------------- layer-2 scatter: half-warp per edge (16 x float4 = 64) -----
__global__ void __launch_bounds__(256)
scatter2_kernel(const int* __restrict__ ei, int E) {
    long long t = (long long)blockIdx.x * blockDim.x + threadIdx.x;
    int edge = (int)(t >> 4);
    int lane = threadIdx.x & 31;
    int comp = lane & 15;
    if (edge >= E) return;
    int s = 0, d = 0;
    if (comp == 0) { s = ei[edge]; d = ei[E + edge]; }
    s = __shfl_sync(0xffffffffu, s, lane & 16);
    d = __shfl_sync(0xffffffffu, d, lane & 16);
    float w = g_dinv2[s] * g_dinv2[d];
    float4 v = reinterpret_cast<const float4*>(g_HG2)[(size_t)s * 16 + comp];
    red_add_v4(&g_A2[(size_t)d * FO + comp * 4], w * v.x, w * v.y, w * v.z,
               w * v.w);
}

// ---------------- finalize layer 1: hidden = A1 + dinv^2*H1 + b1; BN stats ---
__global__ void finalize1_kernel(const float* __restrict__ b1,
                                 float* __restrict__ hidden, int N) {
    int f = threadIdx.x;  // 128 threads = features
    int r0 = blockIdx.x * 64;
    int r1 = min(r0 + 64, N);
    float bias = b1[f];
    float s = 0.f, sq = 0.f;
    for (int r = r0; r < r1; ++r) {
        float di = g_dinv1[r];
        float v = g_A1[(size_t)r * FH + f] + di * di * g_H1[(size_t)r * FH + f] + bias;
        hidden[(size_t)r * FH + f] = v;
        s += v;
        sq += v * v;
    }
    atomicAdd(&g_sum[f], s);
    atomicAdd(&g_sumsq[f], sq);
}

// ---------------- BN scale/shift from batch stats ----------------------------
__global__ void bnprep_kernel(const float* __restrict__ gamma,
                              const float* __restrict__ beta, float invN) {
    int f = threadIdx.x;
    float mean = g_sum[f] * invN;
    float var  = g_sumsq[f] * invN - mean * mean;  // biased, like torch BN
    float sc = gamma[f] * rsqrtf(var + 1e-5f);
    g_scale[f] = sc;
    g_shift[f] = beta[f] - mean * sc;
}

// ---------------- finalize layer 2: out = A2 + dinv2^2*HG2 + b2 --------------
__global__ void finalize2_kernel(const float* __restrict__ b2,
                                 float* __restrict__ out, int N) {
    int i = blockIdx.x * blockDim.x + threadIdx.x;
    if (i < N * FO) {
        int r = i >> 6, f = i & 63;
        float di = g_dinv2[r];
        out[i] = g_A2[i] + di * di * g_HG2[i] + b2[f];
    }
}

// ---------------- launch -----------------------------------------------------
extern "C" void kernel_launch(void* const* d_in, const int* in_sizes, int n_in,
                              void* d_out, int out_size) {
    const float* x     = (const float*)d_in[0];
    const int*   e1    = (const int*)d_in[1];
    const int*   e2    = (const int*)d_in[2];
    const float* W1    = (const float*)d_in[3];
    const float* b1    = (const float*)d_in[4];
    const float* gamma = (const float*)d_in[5];
    const float* beta  = (const float*)d_in[6];
    const float* W2    = (const float*)d_in[7];
    const float* b2    = (const float*)d_in[8];

    int N = in_sizes[0] / FH;
    int E = in_sizes[1] / 2;

    float* out    = (float*)d_out;            // [N, 64]
    float* hidden = out + (size_t)N * FO;     // [N, 128]

    zero_kernel<<<(N * FH + 255) / 256, 256>>>(N);
    deg_kernel<<<(E + 255) / 256, 256>>>(e1, e2, E);
    dinv_kernel<<<(N + 255) / 256, 256>>>(N);

    int gm = (N + 127) / 128;

    // layer 1
    gemm_kernel<false><<<dim3(gm, 2), 256>>>(x, W1, N);
    scatter1_kernel<<<(E * 32 + 255) / 256, 256>>>(e1, E);
    finalize1_kernel<<<(N + 63) / 64, FH>>>(b1, hidden, N);
    bnprep_kernel<<<1, FH>>>(gamma, beta, 1.0f / (float)N);

    // layer 2 (BN + ReLU fused into GEMM2 operand load)
    gemm_kernel<true><<<dim3(gm, 1), 256>>>(hidden, W2, N);
    scatter2_kernel<<<(E * 16 + 255) / 256, 256>>>(e2, E);
    finalize2_kernel<<<(N * FO + 255) / 256, 256>>>(b2, out, N);
}

// round 8
// speedup vs baseline: 1.9095x; 1.1709x over previous
#include <cuda_runtime.h>

#define FH 128
#define FO 64
#define NMAX 50048
#define EMAX 800000

// ---------------- scratch (device globals: no allocation allowed) ------------
__device__ float g_H1[(size_t)NMAX * FH];   // x @ W1
__device__ float g_HG2[(size_t)NMAX * FO];  // bnrelu(hidden) @ W2
__device__ float g_dinv1[NMAX];
__device__ float g_dinv2[NMAX];
__device__ int   g_cnt1[NMAX];
__device__ int   g_cnt2[NMAX];
__device__ int   g_off1[NMAX + 1];
__device__ int   g_off2[NMAX + 1];
__device__ int   g_pos1[NMAX];
__device__ int   g_pos2[NMAX];
__device__ int   g_csr1[EMAX];
__device__ int   g_csr2[EMAX];
__device__ float g_sum[FH];
__device__ float g_sumsq[FH];
__device__ float g_scale[FH];
__device__ float g_shift[FH];

// ---------------- zero counters ----------------------------------------------
__global__ void zero_kernel(int N) {
    int i = blockIdx.x * blockDim.x + threadIdx.x;
    if (i < N) { g_cnt1[i] = 0; g_cnt2[i] = 0; g_pos1[i] = 0; g_pos2[i] = 0; }
    if (i < FH) { g_sum[i] = 0.f; g_sumsq[i] = 0.f; }
}

// ---------------- degree count (dst side, both graphs) -----------------------
__global__ void deg_kernel(const int* __restrict__ e1,
                           const int* __restrict__ e2, int E) {
    int i = blockIdx.x * blockDim.x + threadIdx.x;
    if (i < E) {
        atomicAdd(&g_cnt1[e1[E + i]], 1);
        atomicAdd(&g_cnt2[e2[E + i]], 1);
    }
}

__global__ void dinv_kernel(int N) {
    int i = blockIdx.x * blockDim.x + threadIdx.x;
    if (i < N) {
        g_dinv1[i] = rsqrtf((float)g_cnt1[i] + 1.0f);  // +1 = self loop
        g_dinv2[i] = rsqrtf((float)g_cnt2[i] + 1.0f);
    }
}

// ---------------- exclusive scan of counts -> row offsets (one block/graph) --
__global__ void __launch_bounds__(1024) scan_kernel(int N) {
    const int* cnt = blockIdx.x ? g_cnt2 : g_cnt1;
    int*       off = blockIdx.x ? g_off2 : g_off1;
    __shared__ int ssum[1024];
    int t = threadIdx.x;
    int C = (N + 1023) / 1024;
    int lo = t * C, hi = min(lo + C, N);
    int s = 0;
    for (int i = lo; i < hi; i++) s += cnt[i];
    ssum[t] = s;
    __syncthreads();
    for (int d = 1; d < 1024; d <<= 1) {
        int v = (t >= d) ? ssum[t - d] : 0;
        __syncthreads();
        ssum[t] += v;
        __syncthreads();
    }
    int run = (t == 0) ? 0 : ssum[t - 1];
    for (int i = lo; i < hi; i++) { off[i] = run; run += cnt[i]; }
    if (t == 1023) off[N] = ssum[1023];
}

// ---------------- CSR fill: csr[off[dst] + slot] = src -----------------------
__global__ void fill_kernel(const int* __restrict__ e1,
                            const int* __restrict__ e2, int E) {
    int i = blockIdx.x * blockDim.x + threadIdx.x;
    if (i < E) {
        int s = e1[i], d = e1[E + i];
        int slot = atomicAdd(&g_pos1[d], 1);
        g_csr1[g_off1[d] + slot] = s;
    } else if (i < 2 * E) {
        int j = i - E;
        int s = e2[j], d = e2[E + j];
        int slot = atomicAdd(&g_pos2[d], 1);
        g_csr2[g_off2[d] + slot] = s;
    }
}

// ---------------- GEMM: out[:, col0:col0+64] = X[N x 128] @ W[128 x LD] ------
// BM=128, BN=64, BK=32, 256 threads, 8x4 register tile. Static smem only.
// DO_BN: y = max(0, x*scale[k]+shift[k]) applied to X while loading (layer 2).
template <bool DO_BN>
__global__ void __launch_bounds__(256)
gemm_kernel(const float* __restrict__ X, const float* __restrict__ W, int N) {
    constexpr int LD = DO_BN ? FO : FH;
    __shared__ float XsT[32][132];
    __shared__ float Ws[32][68];
    float* out = DO_BN ? g_HG2 : g_H1;

    const int row0 = blockIdx.x * 128;
    const int col0 = blockIdx.y * 64;
    const int tid  = threadIdx.x;
    const int tx   = tid & 15;
    const int ty   = tid >> 4;

    float acc[8][4];
#pragma unroll
    for (int i = 0; i < 8; i++)
#pragma unroll
        for (int j = 0; j < 4; j++) acc[i][j] = 0.f;

    for (int kc = 0; kc < FH; kc += 32) {
        __syncthreads();
        for (int i = tid; i < 1024; i += 256) {
            int r = i >> 3, c4 = i & 7;
            int row = row0 + r;
            float4 v = make_float4(0.f, 0.f, 0.f, 0.f);
            if (row < N)
                v = reinterpret_cast<const float4*>(X + (size_t)row * FH + kc)[c4];
            int k0 = c4 * 4;
            if (DO_BN) {
                int g = kc + k0;
                v.x = fmaxf(fmaf(v.x, g_scale[g + 0], g_shift[g + 0]), 0.f);
                v.y = fmaxf(fmaf(v.y, g_scale[g + 1], g_shift[g + 1]), 0.f);
                v.z = fmaxf(fmaf(v.z, g_scale[g + 2], g_shift[g + 2]), 0.f);
                v.w = fmaxf(fmaf(v.w, g_scale[g + 3], g_shift[g + 3]), 0.f);
            }
            XsT[k0 + 0][r] = v.x;
            XsT[k0 + 1][r] = v.y;
            XsT[k0 + 2][r] = v.z;
            XsT[k0 + 3][r] = v.w;
        }
        for (int i = tid; i < 512; i += 256) {
            int k = i >> 4, c4 = i & 15;
            reinterpret_cast<float4*>(&Ws[k][0])[c4] =
                reinterpret_cast<const float4*>(W + (size_t)(kc + k) * LD + col0)[c4];
        }
        __syncthreads();

#pragma unroll
        for (int k = 0; k < 32; ++k) {
            float4 a0 = *reinterpret_cast<const float4*>(&XsT[k][ty * 8]);
            float4 a1 = *reinterpret_cast<const float4*>(&XsT[k][ty * 8 + 4]);
            float4 b  = *reinterpret_cast<const float4*>(&Ws[k][tx * 4]);
            float av[8] = {a0.x, a0.y, a0.z, a0.w, a1.x, a1.y, a1.z, a1.w};
            float bv[4] = {b.x, b.y, b.z, b.w};
#pragma unroll
            for (int i = 0; i < 8; i++)
#pragma unroll
                for (int j = 0; j < 4; j++)
                    acc[i][j] = fmaf(av[i], bv[j], acc[i][j]);
        }
    }

#pragma unroll
    for (int i = 0; i < 8; i++) {
        int row = row0 + ty * 8 + i;
        if (row < N) {
            *reinterpret_cast<float4*>(&out[(size_t)row * LD + col0 + tx * 4]) =
                make_float4(acc[i][0], acc[i][1], acc[i][2], acc[i][3]);
        }
    }
}

// ---------------- gather layer 1 (warp/node, fused bias+selfloop+BN stats) ---
__global__ void __launch_bounds__(256)
gather1_kernel(const float* __restrict__ b1, float* __restrict__ hidden, int N) {
    __shared__ float s_s[FH], s_q[FH];
    int tid = threadIdx.x;
    if (tid < FH) { s_s[tid] = 0.f; s_q[tid] = 0.f; }
    __syncthreads();

    int node = blockIdx.x * 8 + (tid >> 5);
    int lane = tid & 31;
    if (node < N) {
        int beg = g_off1[node], end = g_off1[node + 1];
        float4 acc = make_float4(0.f, 0.f, 0.f, 0.f);
        const float4* H = reinterpret_cast<const float4*>(g_H1);
        int j = beg;
        for (; j + 4 <= end; j += 4) {
            int s0 = g_csr1[j], s1 = g_csr1[j + 1];
            int s2 = g_csr1[j + 2], s3 = g_csr1[j + 3];
            float w0 = g_dinv1[s0], w1 = g_dinv1[s1];
            float w2 = g_dinv1[s2], w3 = g_dinv1[s3];
            float4 v0 = H[(size_t)s0 * 32 + lane];
            float4 v1 = H[(size_t)s1 * 32 + lane];
            float4 v2 = H[(size_t)s2 * 32 + lane];
            float4 v3 = H[(size_t)s3 * 32 + lane];
            acc.x += w0 * v0.x + w1 * v1.x + w2 * v2.x + w3 * v3.x;
            acc.y += w0 * v0.y + w1 * v1.y + w2 * v2.y + w3 * v3.y;
            acc.z += w0 * v0.z + w1 * v1.z + w2 * v2.z + w3 * v3.z;
            acc.w += w0 * v0.w + w1 * v1.w + w2 * v2.w + w3 * v3.w;
        }
        for (; j < end; ++j) {
            int s = g_csr1[j];
            float w = g_dinv1[s];
            float4 v = H[(size_t)s * 32 + lane];
            acc.x += w * v.x; acc.y += w * v.y;
            acc.z += w * v.z; acc.w += w * v.w;
        }
        float di = g_dinv1[node];
        float4 h  = H[(size_t)node * 32 + lane];
        float4 bb = reinterpret_cast<const float4*>(b1)[lane];
        float4 v;
        v.x = di * acc.x + di * di * h.x + bb.x;
        v.y = di * acc.y + di * di * h.y + bb.y;
        v.z = di * acc.z + di * di * h.z + bb.z;
        v.w = di * acc.w + di * di * h.w + bb.w;
        reinterpret_cast<float4*>(hidden)[(size_t)node * 32 + lane] = v;
        int f = lane * 4;
        atomicAdd(&s_s[f + 0], v.x); atomicAdd(&s_q[f + 0], v.x * v.x);
        atomicAdd(&s_s[f + 1], v.y); atomicAdd(&s_q[f + 1], v.y * v.y);
        atomicAdd(&s_s[f + 2], v.z); atomicAdd(&s_q[f + 2], v.z * v.z);
        atomicAdd(&s_s[f + 3], v.w); atomicAdd(&s_q[f + 3], v.w * v.w);
    }
    __syncthreads();
    if (tid < FH) {
        atomicAdd(&g_sum[tid], s_s[tid]);
        atomicAdd(&g_sumsq[tid], s_q[tid]);
    }
}

// ---------------- BN scale/shift from batch stats ----------------------------
__global__ void bnprep_kernel(const float* __restrict__ gamma,
                              const float* __restrict__ beta, float invN) {
    int f = threadIdx.x;
    float mean = g_sum[f] * invN;
    float var  = g_sumsq[f] * invN - mean * mean;  // biased, like torch BN
    float sc = gamma[f] * rsqrtf(var + 1e-5f);
    g_scale[f] = sc;
    g_shift[f] = beta[f] - mean * sc;
}

// ---------------- gather layer 2 (warp/node, float2 lanes, fused epilogue) ---
__global__ void __launch_bounds__(256)
gather2_kernel(const float* __restrict__ b2, float* __restrict__ out, int N) {
    int tid = threadIdx.x;
    int node = blockIdx.x * 8 + (tid >> 5);
    int lane = tid & 31;
    if (node >= N) return;
    int beg = g_off2[node], end = g_off2[node + 1];
    float2 acc = make_float2(0.f, 0.f);
    const float2* H = reinterpret_cast<const float2*>(g_HG2);
    int j = beg;
    for (; j + 4 <= end; j += 4) {
        int s0 = g_csr2[j], s1 = g_csr2[j + 1];
        int s2 = g_csr2[j + 2], s3 = g_csr2[j + 3];
        float w0 = g_dinv2[s0], w1 = g_dinv2[s1];
        float w2 = g_dinv2[s2], w3 = g_dinv2[s3];
        float2 v0 = H[(size_t)s0 * 32 + lane];
        float2 v1 = H[(size_t)s1 * 32 + lane];
        float2 v2 = H[(size_t)s2 * 32 + lane];
        float2 v3 = H[(size_t)s3 * 32 + lane];
        acc.x += w0 * v0.x + w1 * v1.x + w2 * v2.x + w3 * v3.x;
        acc.y += w0 * v0.y + w1 * v1.y + w2 * v2.y + w3 * v3.y;
    }
    for (; j < end; ++j) {
        int s = g_csr2[j];
        float w = g_dinv2[s];
        float2 v = H[(size_t)s * 32 + lane];
        acc.x += w * v.x; acc.y += w * v.y;
    }
    float di = g_dinv2[node];
    float2 h  = H[(size_t)node * 32 + lane];
    float2 bb = reinterpret_cast<const float2*>(b2)[lane];
    float2 v;
    v.x = di * acc.x + di * di * h.x + bb.x;
    v.y = di * acc.y + di * di * h.y + bb.y;
    reinterpret_cast<float2*>(out)[(size_t)node * 32 + lane] = v;
}

// ---------------- launch -----------------------------------------------------
extern "C" void kernel_launch(void* const* d_in, const int* in_sizes, int n_in,
                              void* d_out, int out_size) {
    const float* x     = (const float*)d_in[0];
    const int*   e1    = (const int*)d_in[1];
    const int*   e2    = (const int*)d_in[2];
    const float* W1    = (const float*)d_in[3];
    const float* b1    = (const float*)d_in[4];
    const float* gamma = (const float*)d_in[5];
    const float* beta  = (const float*)d_in[6];
    const float* W2    = (const float*)d_in[7];
    const float* b2    = (const float*)d_in[8];

    int N = in_sizes[0] / FH;
    int E = in_sizes[1] / 2;

    float* out    = (float*)d_out;            // [N, 64]
    float* hidden = out + (size_t)N * FO;     // [N, 128]

    // graph prep
    zero_kernel<<<(N + 255) / 256, 256>>>(N);
    deg_kernel<<<(E + 255) / 256, 256>>>(e1, e2, E);
    dinv_kernel<<<(N + 255) / 256, 256>>>(N);
    scan_kernel<<<2, 1024>>>(N);
    fill_kernel<<<(2 * E + 255) / 256, 256>>>(e1, e2, E);

    int gm = (N + 127) / 128;
    int gn = (N + 7) / 8;

    // layer 1
    gemm_kernel<false><<<dim3(gm, 2), 256>>>(x, W1, N);
    gather1_kernel<<<gn, 256>>>(b1, hidden, N);
    bnprep_kernel<<<1, FH>>>(gamma, beta, 1.0f / (float)N);

    // layer 2 (BN + ReLU fused into GEMM2 operand load)
    gemm_kernel<true><<<dim3(gm, 1), 256>>>(hidden, W2, N);
    gather2_kernel<<<gn, 256>>>(b2, out, N);
}

// round 9
// speedup vs baseline: 2.0873x; 1.0931x over previous
#include <cuda_runtime.h>

#define FH 128
#define FO 64
#define NMAX 50048
#define EMAX 800000
#define SCAN_B 1024
#define NBLK ((NMAX + SCAN_B - 1) / SCAN_B)   // 49

// ---------------- scratch (device globals: no allocation allowed) ------------
__device__ float g_H1[(size_t)NMAX * FH];   // x @ W1
__device__ float g_HG2[(size_t)NMAX * FO];  // bnrelu(hidden) @ W2
__device__ float g_dinv1[NMAX];
__device__ float g_dinv2[NMAX];
__device__ int   g_cnt1[NMAX];
__device__ int   g_cnt2[NMAX];
__device__ int   g_off1[NMAX + 1];
__device__ int   g_off2[NMAX + 1];
__device__ int   g_pos1[NMAX];
__device__ int   g_pos2[NMAX];
__device__ int   g_csr1[EMAX];
__device__ int   g_csr2[EMAX];
__device__ int   g_bsum[2][NBLK];
__device__ float g_sum[FH];
__device__ float g_sumsq[FH];
__device__ float g_scale[FH];
__device__ float g_shift[FH];

// ---------------- zero counters ----------------------------------------------
__global__ void zero_kernel(int N) {
    int i = blockIdx.x * blockDim.x + threadIdx.x;
    if (i < N) { g_cnt1[i] = 0; g_cnt2[i] = 0; g_pos1[i] = 0; g_pos2[i] = 0; }
    if (i < FH) { g_sum[i] = 0.f; g_sumsq[i] = 0.f; }
}

// ---------------- degree count (dst side, both graphs) -----------------------
__global__ void deg_kernel(const int* __restrict__ e1,
                           const int* __restrict__ e2, int E) {
    int i = blockIdx.x * blockDim.x + threadIdx.x;
    if (i < E) {
        atomicAdd(&g_cnt1[e1[E + i]], 1);
        atomicAdd(&g_cnt2[e2[E + i]], 1);
    }
}

__global__ void dinv_kernel(int N) {
    int i = blockIdx.x * blockDim.x + threadIdx.x;
    if (i < N) {
        g_dinv1[i] = rsqrtf((float)g_cnt1[i] + 1.0f);  // +1 = self loop
        g_dinv2[i] = rsqrtf((float)g_cnt2[i] + 1.0f);
    }
}

// ---------------- hierarchical scan, phase A: per-block scan + totals --------
__global__ void __launch_bounds__(SCAN_B) scanA_kernel(int N) {
    const int* cnt = blockIdx.y ? g_cnt2 : g_cnt1;
    int*       off = blockIdx.y ? g_off2 : g_off1;
    __shared__ int sh[SCAN_B];
    int t = threadIdx.x;
    int i = blockIdx.x * SCAN_B + t;
    int v = (i < N) ? cnt[i] : 0;
    sh[t] = v;
    __syncthreads();
    // Hillis-Steele inclusive scan
#pragma unroll
    for (int d = 1; d < SCAN_B; d <<= 1) {
        int u = (t >= d) ? sh[t - d] : 0;
        __syncthreads();
        sh[t] += u;
        __syncthreads();
    }
    if (i < N) off[i] = sh[t] - v;  // local exclusive prefix
    if (t == SCAN_B - 1) g_bsum[blockIdx.y][blockIdx.x] = sh[t];
}

// ---------------- phase B: scan the block totals (serial, tiny) --------------
__global__ void scanB_kernel(int N, int nb) {
    int g = threadIdx.x;  // 2 threads, one per graph
    if (g >= 2) return;
    int run = 0;
    for (int b = 0; b < nb; b++) {
        int v = g_bsum[g][b];
        g_bsum[g][b] = run;
        run += v;
    }
    if (g == 0) g_off1[N] = run; else g_off2[N] = run;
}

// ---------------- phase C: add block bases -----------------------------------
__global__ void __launch_bounds__(SCAN_B) scanC_kernel(int N) {
    int* off = blockIdx.y ? g_off2 : g_off1;
    int base = g_bsum[blockIdx.y][blockIdx.x];
    int i = blockIdx.x * SCAN_B + threadIdx.x;
    if (i < N) off[i] += base;
}

// ---------------- CSR fill: csr[off[dst] + slot] = src -----------------------
__global__ void fill_kernel(const int* __restrict__ e1,
                            const int* __restrict__ e2, int E) {
    int i = blockIdx.x * blockDim.x + threadIdx.x;
    if (i < E) {
        int s = e1[i], d = e1[E + i];
        int slot = atomicAdd(&g_pos1[d], 1);
        g_csr1[g_off1[d] + slot] = s;
    } else if (i < 2 * E) {
        int j = i - E;
        int s = e2[j], d = e2[E + j];
        int slot = atomicAdd(&g_pos2[d], 1);
        g_csr2[g_off2[d] + slot] = s;
    }
}

// ---------------- GEMM: out[:, col0:col0+64] = X[N x 128] @ W[128 x LD] ------
template <bool DO_BN>
__global__ void __launch_bounds__(256)
gemm_kernel(const float* __restrict__ X, const float* __restrict__ W, int N) {
    constexpr int LD = DO_BN ? FO : FH;
    __shared__ float XsT[32][132];
    __shared__ float Ws[32][68];
    float* out = DO_BN ? g_HG2 : g_H1;

    const int row0 = blockIdx.x * 128;
    const int col0 = blockIdx.y * 64;
    const int tid  = threadIdx.x;
    const int tx   = tid & 15;
    const int ty   = tid >> 4;

    float acc[8][4];
#pragma unroll
    for (int i = 0; i < 8; i++)
#pragma unroll
        for (int j = 0; j < 4; j++) acc[i][j] = 0.f;

    for (int kc = 0; kc < FH; kc += 32) {
        __syncthreads();
        for (int i = tid; i < 1024; i += 256) {
            int r = i >> 3, c4 = i & 7;
            int row = row0 + r;
            float4 v = make_float4(0.f, 0.f, 0.f, 0.f);
            if (row < N)
                v = reinterpret_cast<const float4*>(X + (size_t)row * FH + kc)[c4];
            int k0 = c4 * 4;
            if (DO_BN) {
                int g = kc + k0;
                v.x = fmaxf(fmaf(v.x, g_scale[g + 0], g_shift[g + 0]), 0.f);
                v.y = fmaxf(fmaf(v.y, g_scale[g + 1], g_shift[g + 1]), 0.f);
                v.z = fmaxf(fmaf(v.z, g_scale[g + 2], g_shift[g + 2]), 0.f);
                v.w = fmaxf(fmaf(v.w, g_scale[g + 3], g_shift[g + 3]), 0.f);
            }
            XsT[k0 + 0][r] = v.x;
            XsT[k0 + 1][r] = v.y;
            XsT[k0 + 2][r] = v.z;
            XsT[k0 + 3][r] = v.w;
        }
        for (int i = tid; i < 512; i += 256) {
            int k = i >> 4, c4 = i & 15;
            reinterpret_cast<float4*>(&Ws[k][0])[c4] =
                reinterpret_cast<const float4*>(W + (size_t)(kc + k) * LD + col0)[c4];
        }
        __syncthreads();

#pragma unroll
        for (int k = 0; k < 32; ++k) {
            float4 a0 = *reinterpret_cast<const float4*>(&XsT[k][ty * 8]);
            float4 a1 = *reinterpret_cast<const float4*>(&XsT[k][ty * 8 + 4]);
            float4 b  = *reinterpret_cast<const float4*>(&Ws[k][tx * 4]);
            float av[8] = {a0.x, a0.y, a0.z, a0.w, a1.x, a1.y, a1.z, a1.w};
            float bv[4] = {b.x, b.y, b.z, b.w};
#pragma unroll
            for (int i = 0; i < 8; i++)
#pragma unroll
                for (int j = 0; j < 4; j++)
                    acc[i][j] = fmaf(av[i], bv[j], acc[i][j]);
        }
    }

#pragma unroll
    for (int i = 0; i < 8; i++) {
        int row = row0 + ty * 8 + i;
        if (row < N) {
            *reinterpret_cast<float4*>(&out[(size_t)row * LD + col0 + tx * 4]) =
                make_float4(acc[i][0], acc[i][1], acc[i][2], acc[i][3]);
        }
    }
}

// ---------------- gather layer 1 (warp/node, fused bias+selfloop+BN stats) ---
__global__ void __launch_bounds__(256)
gather1_kernel(const float* __restrict__ b1, float* __restrict__ hidden, int N) {
    __shared__ float s_s[FH], s_q[FH];
    int tid = threadIdx.x;
    if (tid < FH) { s_s[tid] = 0.f; s_q[tid] = 0.f; }
    __syncthreads();

    int node = blockIdx.x * 8 + (tid >> 5);
    int lane = tid & 31;
    if (node < N) {
        int beg = g_off1[node], end = g_off1[node + 1];
        float4 acc = make_float4(0.f, 0.f, 0.f, 0.f);
        const float4* H = reinterpret_cast<const float4*>(g_H1);
        int j = beg;
        for (; j + 4 <= end; j += 4) {
            int s0 = g_csr1[j], s1 = g_csr1[j + 1];
            int s2 = g_csr1[j + 2], s3 = g_csr1[j + 3];
            float w0 = g_dinv1[s0], w1 = g_dinv1[s1];
            float w2 = g_dinv1[s2], w3 = g_dinv1[s3];
            float4 v0 = H[(size_t)s0 * 32 + lane];
            float4 v1 = H[(size_t)s1 * 32 + lane];
            float4 v2 = H[(size_t)s2 * 32 + lane];
            float4 v3 = H[(size_t)s3 * 32 + lane];
            acc.x += w0 * v0.x + w1 * v1.x + w2 * v2.x + w3 * v3.x;
            acc.y += w0 * v0.y + w1 * v1.y + w2 * v2.y + w3 * v3.y;
            acc.z += w0 * v0.z + w1 * v1.z + w2 * v2.z + w3 * v3.z;
            acc.w += w0 * v0.w + w1 * v1.w + w2 * v2.w + w3 * v3.w;
        }
        for (; j < end; ++j) {
            int s = g_csr1[j];
            float w = g_dinv1[s];
            float4 v = H[(size_t)s * 32 + lane];
            acc.x += w * v.x; acc.y += w * v.y;
            acc.z += w * v.z; acc.w += w * v.w;
        }
        float di = g_dinv1[node];
        float4 h  = H[(size_t)node * 32 + lane];
        float4 bb = reinterpret_cast<const float4*>(b1)[lane];
        float4 v;
        v.x = di * acc.x + di * di * h.x + bb.x;
        v.y = di * acc.y + di * di * h.y + bb.y;
        v.z = di * acc.z + di * di * h.z + bb.z;
        v.w = di * acc.w + di * di * h.w + bb.w;
        reinterpret_cast<float4*>(hidden)[(size_t)node * 32 + lane] = v;
        int f = lane * 4;
        atomicAdd(&s_s[f + 0], v.x); atomicAdd(&s_q[f + 0], v.x * v.x);
        atomicAdd(&s_s[f + 1], v.y); atomicAdd(&s_q[f + 1], v.y * v.y);
        atomicAdd(&s_s[f + 2], v.z); atomicAdd(&s_q[f + 2], v.z * v.z);
        atomicAdd(&s_s[f + 3], v.w); atomicAdd(&s_q[f + 3], v.w * v.w);
    }
    __syncthreads();
    if (tid < FH) {
        atomicAdd(&g_sum[tid], s_s[tid]);
        atomicAdd(&g_sumsq[tid], s_q[tid]);
    }
}

// ---------------- BN scale/shift from batch stats ----------------------------
__global__ void bnprep_kernel(const float* __restrict__ gamma,
                              const float* __restrict__ beta, float invN) {
    int f = threadIdx.x;
    float mean = g_sum[f] * invN;
    float var  = g_sumsq[f] * invN - mean * mean;  // biased, like torch BN
    float sc = gamma[f] * rsqrtf(var + 1e-5f);
    g_scale[f] = sc;
    g_shift[f] = beta[f] - mean * sc;
}

// ---------------- gather layer 2 (warp/node, float2 lanes, fused epilogue) ---
__global__ void __launch_bounds__(256)
gather2_kernel(const float* __restrict__ b2, float* __restrict__ out, int N) {
    int tid = threadIdx.x;
    int node = blockIdx.x * 8 + (tid >> 5);
    int lane = tid & 31;
    if (node >= N) return;
    int beg = g_off2[node], end = g_off2[node + 1];
    float2 acc = make_float2(0.f, 0.f);
    const float2* H = reinterpret_cast<const float2*>(g_HG2);
    int j = beg;
    for (; j + 4 <= end; j += 4) {
        int s0 = g_csr2[j], s1 = g_csr2[j + 1];
        int s2 = g_csr2[j + 2], s3 = g_csr2[j + 3];
        float w0 = g_dinv2[s0], w1 = g_dinv2[s1];
        float w2 = g_dinv2[s2], w3 = g_dinv2[s3];
        float2 v0 = H[(size_t)s0 * 32 + lane];
        float2 v1 = H[(size_t)s1 * 32 + lane];
        float2 v2 = H[(size_t)s2 * 32 + lane];
        float2 v3 = H[(size_t)s3 * 32 + lane];
        acc.x += w0 * v0.x + w1 * v1.x + w2 * v2.x + w3 * v3.x;
        acc.y += w0 * v0.y + w1 * v1.y + w2 * v2.y + w3 * v3.y;
    }
    for (; j < end; ++j) {
        int s = g_csr2[j];
        float w = g_dinv2[s];
        float2 v = H[(size_t)s * 32 + lane];
        acc.x += w * v.x; acc.y += w * v.y;
    }
    float di = g_dinv2[node];
    float2 h  = H[(size_t)node * 32 + lane];
    float2 bb = reinterpret_cast<const float2*>(b2)[lane];
    float2 v;
    v.x = di * acc.x + di * di * h.x + bb.x;
    v.y = di * acc.y + di * di * h.y + bb.y;
    reinterpret_cast<float2*>(out)[(size_t)node * 32 + lane] = v;
}

// ---------------- launch -----------------------------------------------------
extern "C" void kernel_launch(void* const* d_in, const int* in_sizes, int n_in,
                              void* d_out, int out_size) {
    const float* x     = (const float*)d_in[0];
    const int*   e1    = (const int*)d_in[1];
    const int*   e2    = (const int*)d_in[2];
    const float* W1    = (const float*)d_in[3];
    const float* b1    = (const float*)d_in[4];
    const float* gamma = (const float*)d_in[5];
    const float* beta  = (const float*)d_in[6];
    const float* W2    = (const float*)d_in[7];
    const float* b2    = (const float*)d_in[8];

    int N = in_sizes[0] / FH;
    int E = in_sizes[1] / 2;

    float* out    = (float*)d_out;            // [N, 64]
    float* hidden = out + (size_t)N * FO;     // [N, 128]

    int nb = (N + SCAN_B - 1) / SCAN_B;

    // graph prep
    zero_kernel<<<(N + 255) / 256, 256>>>(N);
    deg_kernel<<<(E + 255) / 256, 256>>>(e1, e2, E);
    dinv_kernel<<<(N + 255) / 256, 256>>>(N);
    scanA_kernel<<<dim3(nb, 2), SCAN_B>>>(N);
    scanB_kernel<<<1, 32>>>(N, nb);
    scanC_kernel<<<dim3(nb, 2), SCAN_B>>>(N);
    fill_kernel<<<(2 * E + 255) / 256, 256>>>(e1, e2, E);

    int gm = (N + 127) / 128;
    int gn = (N + 7) / 8;

    // layer 1
    gemm_kernel<false><<<dim3(gm, 2), 256>>>(x, W1, N);
    gather1_kernel<<<gn, 256>>>(b1, hidden, N);
    bnprep_kernel<<<1, FH>>>(gamma, beta, 1.0f / (float)N);

    // layer 2 (BN + ReLU fused into GEMM2 operand load)
    gemm_kernel<true><<<dim3(gm, 1), 256>>>(hidden, W2, N);
    gather2_kernel<<<gn, 256>>>(b2, out, N);
}